// round 5
// baseline (speedup 1.0000x reference)
#include <cuda_runtime.h>

#define VOCAB 50257
#define EMB   512
#define HID   1024
#define TT    512
#define BB    64
#define NG    4096        // 4*HID
#define LSCALE 2.0f       // ALPHA / R
#define NCTA  128         // persistent recurrent grid

// ---------------- scratch (static device globals; no allocation) ----------------
__device__ float g_Wih0t[EMB * NG];           // [K=512][4096]  x-proj weights (original gate order)
__device__ float g_Wih1t[HID * NG];           // [K=1024][4096]
__device__ float g_Whh0r[HID * NG];           // [K=1024][4096] gate-interleaved cols: c = j*4 + q
__device__ float g_Whh1r[HID * NG];
__device__ float g_bsum0[NG];
__device__ float g_bsum1[NG];
__device__ float g_xproj[(size_t)TT * BB * NG];    // 512 MB, reused by both layers
__device__ float g_h0seq[(size_t)TT * BB * HID];   // layer-0 hidden states for all t
__device__ float g_hbuf[2 * BB * HID];             // layer-1 h ping-pong
__device__ float g_cbuf[2 * BB * HID];             // c ping-pong (reused per layer)
__device__ float g_zero[BB * HID];                 // zeroed each launch

// software grid-barrier state (reset every launch for replay determinism)
__device__ unsigned g_bar_count;
__device__ volatile unsigned g_bar_sense;

// ---------------- utility kernels ----------------
__global__ void zero_kernel() {
    int i = blockIdx.x * blockDim.x + threadIdx.x;
    if (i < BB * HID) g_zero[i] = 0.0f;
    if (i == 0) { g_bar_count = 0; g_bar_sense = 0; }
}

// Build effective weights: W_eff = W + LSCALE * B@A, written transposed.
// mode 0: out[k*NG + g]  = W[g*K + k] + ...          (original gate order; input projections)
// mode 1: out[k*NG + c], c = j*4+q, g = q*HID + j    (gate-interleaved; recurrent weights)
__global__ void prep_w_kernel(const float* __restrict__ W,
                              const float* __restrict__ A,
                              const float* __restrict__ Bm,
                              int K, int mode, int which) {
    int idx = blockIdx.x * blockDim.x + threadIdx.x;
    if (idx >= K * NG) return;
    int col = idx % NG;
    int k   = idx / NG;
    int g;
    if (mode == 0) g = col;
    else { int j = col >> 2; int q = col & 3; g = q * HID + j; }
    float s = 0.0f;
#pragma unroll
    for (int r = 0; r < 8; r++) s += Bm[g * 8 + r] * A[r * K + k];
    float v = W[(size_t)g * K + k] + LSCALE * s;
    float* out = (which == 0) ? g_Wih0t : (which == 1) ? g_Wih1t
               : (which == 2) ? g_Whh0r : g_Whh1r;
    out[(size_t)k * NG + col] = v;
}

__global__ void prep_bias_kernel(const float* __restrict__ bih0, const float* __restrict__ bhh0,
                                 const float* __restrict__ bih1, const float* __restrict__ bhh1) {
    int i = blockIdx.x * blockDim.x + threadIdx.x;
    if (i < NG)           g_bsum0[i]       = bih0[i] + bhh0[i];
    else if (i < 2 * NG)  g_bsum1[i - NG]  = bih1[i - NG] + bhh1[i - NG];
}

// ---------------- big GEMM: g_xproj[M=32768][4096] = A[M][K] @ Wt[K][4096] ----------------
// gather=1: A row comes from emb[x[b][t]], K=EMB, Wt=g_Wih0t, blockIdx.y == t
// gather=0: A = g_h0seq, K=HID, Wt=g_Wih1t
__global__ void __launch_bounds__(256)
gemm_kernel(const float* __restrict__ emb, const int* __restrict__ xtok, int K, int gather) {
    __shared__ float As[16 * 68];   // [k][m], padded
    __shared__ float Bs[16 * 68];   // [k][n], padded
    const int bn = blockIdx.x * 64;
    const int bm = blockIdx.y * 64;
    const int tid = threadIdx.x;
    const int tx = tid & 15, ty = tid >> 4;

    const int lrow = tid >> 2;          // 0..63  A-load row
    const int lk   = (tid & 3) * 4;     // 0,4,8,12
    const int bkk  = tid >> 4;          // 0..15  B-load k row
    const int bc   = (tid & 15) * 4;    // 0..60

    const float* __restrict__ Wt = gather ? g_Wih0t : g_Wih1t;
    const float* arow;
    if (gather) {
        int tok = xtok[lrow * TT + blockIdx.y];     // x[b][t], b=lrow, t=blockIdx.y
        arow = emb + (size_t)tok * EMB;
    } else {
        arow = g_h0seq + (size_t)(bm + lrow) * HID;
    }

    float acc[4][4] = {};
    for (int kt = 0; kt < K; kt += 16) {
        float4 av = *(const float4*)(arow + kt + lk);
        float4 bv = *(const float4*)(Wt + (size_t)(kt + bkk) * NG + bn + bc);
        __syncthreads();
        As[(lk + 0) * 68 + lrow] = av.x;
        As[(lk + 1) * 68 + lrow] = av.y;
        As[(lk + 2) * 68 + lrow] = av.z;
        As[(lk + 3) * 68 + lrow] = av.w;
        *(float4*)&Bs[bkk * 68 + bc] = bv;
        __syncthreads();
#pragma unroll
        for (int kk = 0; kk < 16; kk++) {
            float4 a = *(const float4*)&As[kk * 68 + ty * 4];
            float4 b = *(const float4*)&Bs[kk * 68 + tx * 4];
            acc[0][0] += a.x * b.x; acc[0][1] += a.x * b.y; acc[0][2] += a.x * b.z; acc[0][3] += a.x * b.w;
            acc[1][0] += a.y * b.x; acc[1][1] += a.y * b.y; acc[1][2] += a.y * b.z; acc[1][3] += a.y * b.w;
            acc[2][0] += a.z * b.x; acc[2][1] += a.z * b.y; acc[2][2] += a.z * b.z; acc[2][3] += a.z * b.w;
            acc[3][0] += a.w * b.x; acc[3][1] += a.w * b.y; acc[3][2] += a.w * b.z; acc[3][3] += a.w * b.w;
        }
    }
#pragma unroll
    for (int i = 0; i < 4; i++) {
        float4 v = make_float4(acc[i][0], acc[i][1], acc[i][2], acc[i][3]);
        *(float4*)(g_xproj + (size_t)(bm + ty * 4 + i) * NG + bn + tx * 4) = v;
    }
}

// ---------------- persistent recurrent kernel: full 512-step scan for one layer ----------------
// 128 CTAs; CTA owns 32 gate-interleaved cols = 8 hidden units x 4 gates, all 64 batches.
// Internal software grid barrier between steps (all CTAs co-resident: 128 <= 148 SMs).
__global__ void __launch_bounds__(256)
recur_kernel(int layer, const int* __restrict__ lengths, float* __restrict__ fout) {
    __shared__ float hs[64 * 36];   // [b][k] padded stride 36
    __shared__ float ws[32 * 32];   // [k][c]
    const int tid = threadIdx.x;
    const int c0 = blockIdx.x * 32;
    const int jl = tid & 7;
    const int bp = tid >> 3;        // 0..31
    const int b0 = bp * 2;

    const float* __restrict__ Wr   = layer ? g_Whh1r : g_Whh0r;
    const float* __restrict__ bsum = layer ? g_bsum1 : g_bsum0;

    const int hrow = tid >> 2;          // 0..63
    const int hk   = (tid & 3) * 8;     // 0,8,16,24
    const int wkk  = tid >> 3;          // 0..31
    const int wc   = (tid & 7) * 4;     // 0..28
    const int j    = (c0 >> 2) + jl;    // global hidden unit

    unsigned gen = 0;   // zero_kernel resets g_bar_sense to 0 before this launch

    for (int t = 0; t < TT; t++) {
        const float* __restrict__ xpt = g_xproj + (size_t)t * BB * NG;
        const float* hprev; const float* cprev; float* hout; float* cout;
        if (layer == 0) {
            hprev = t ? (g_h0seq + (size_t)(t - 1) * BB * HID) : g_zero;
            hout  = g_h0seq + (size_t)t * BB * HID;
        } else {
            hprev = t ? (g_hbuf + (size_t)((t - 1) & 1) * BB * HID) : g_zero;
            hout  = g_hbuf + (size_t)(t & 1) * BB * HID;
        }
        cprev = t ? (g_cbuf + (size_t)((t - 1) & 1) * BB * HID) : g_zero;
        cout  = g_cbuf + (size_t)(t & 1) * BB * HID;

        float acc[2][4] = {};
        for (int kt = 0; kt < HID; kt += 32) {
            float4 h0v = *(const float4*)(hprev + hrow * HID + kt + hk);
            float4 h1v = *(const float4*)(hprev + hrow * HID + kt + hk + 4);
            float4 wv  = *(const float4*)(Wr + (size_t)(kt + wkk) * NG + c0 + wc);
            __syncthreads();
            *(float4*)&hs[hrow * 36 + hk]     = h0v;
            *(float4*)&hs[hrow * 36 + hk + 4] = h1v;
            *(float4*)&ws[wkk * 32 + wc]      = wv;
            __syncthreads();
#pragma unroll
            for (int k4 = 0; k4 < 32; k4 += 4) {
                float4 ha = *(const float4*)&hs[b0 * 36 + k4];
                float4 hb = *(const float4*)&hs[(b0 + 1) * 36 + k4];
                float4 w0 = *(const float4*)&ws[(k4 + 0) * 32 + jl * 4];
                float4 w1 = *(const float4*)&ws[(k4 + 1) * 32 + jl * 4];
                float4 w2 = *(const float4*)&ws[(k4 + 2) * 32 + jl * 4];
                float4 w3 = *(const float4*)&ws[(k4 + 3) * 32 + jl * 4];
                acc[0][0] += ha.x * w0.x; acc[0][1] += ha.x * w0.y; acc[0][2] += ha.x * w0.z; acc[0][3] += ha.x * w0.w;
                acc[0][0] += ha.y * w1.x; acc[0][1] += ha.y * w1.y; acc[0][2] += ha.y * w1.z; acc[0][3] += ha.y * w1.w;
                acc[0][0] += ha.z * w2.x; acc[0][1] += ha.z * w2.y; acc[0][2] += ha.z * w2.z; acc[0][3] += ha.z * w2.w;
                acc[0][0] += ha.w * w3.x; acc[0][1] += ha.w * w3.y; acc[0][2] += ha.w * w3.z; acc[0][3] += ha.w * w3.w;
                acc[1][0] += hb.x * w0.x; acc[1][1] += hb.x * w0.y; acc[1][2] += hb.x * w0.z; acc[1][3] += hb.x * w0.w;
                acc[1][0] += hb.y * w1.x; acc[1][1] += hb.y * w1.y; acc[1][2] += hb.y * w1.z; acc[1][3] += hb.y * w1.w;
                acc[1][0] += hb.z * w2.x; acc[1][1] += hb.z * w2.y; acc[1][2] += hb.z * w2.z; acc[1][3] += hb.z * w2.w;
                acc[1][0] += hb.w * w3.x; acc[1][1] += hb.w * w3.y; acc[1][2] += hb.w * w3.z; acc[1][3] += hb.w * w3.w;
            }
        }

#pragma unroll
        for (int pb = 0; pb < 2; pb++) {
            int b = b0 + pb;
            float vi = acc[pb][0] + bsum[0 * HID + j] + xpt[b * NG + 0 * HID + j];
            float vf = acc[pb][1] + bsum[1 * HID + j] + xpt[b * NG + 1 * HID + j];
            float vg = acc[pb][2] + bsum[2 * HID + j] + xpt[b * NG + 2 * HID + j];
            float vo = acc[pb][3] + bsum[3 * HID + j] + xpt[b * NG + 3 * HID + j];
            float is = 1.0f / (1.0f + expf(-vi));
            float fs = 1.0f / (1.0f + expf(-vf));
            float gs = tanhf(vg);
            float os = 1.0f / (1.0f + expf(-vo));
            float cn = fs * cprev[b * HID + j] + is * gs;
            float hn = os * tanhf(cn);
            hout[b * HID + j] = hn;
            cout[b * HID + j] = cn;
            if (lengths && (lengths[b] - 1) == t) fout[b * HID + j] = hn;
        }

        // -------- grid barrier (sense-reversal) --------
        __syncthreads();
        if (tid == 0) {
            __threadfence();
            if (atomicAdd(&g_bar_count, 1u) == NCTA - 1) {
                atomicExch(&g_bar_count, 0u);
                __threadfence();
                g_bar_sense = gen + 1;
            } else {
                while (g_bar_sense == gen) { }
                __threadfence();
            }
        }
        __syncthreads();
        gen++;
    }
}

// ---------------- host ----------------
extern "C" void kernel_launch(void* const* d_in, const int* in_sizes, int n_in,
                              void* d_out, int out_size) {
    const int*   x    = (const int*)  d_in[0];
    const int*   lens = (const int*)  d_in[1];
    const float* emb  = (const float*)d_in[2];
    const float* Wih0 = (const float*)d_in[3];
    const float* bih0 = (const float*)d_in[4];
    const float* Aih0 = (const float*)d_in[5];
    const float* Bih0 = (const float*)d_in[6];
    const float* Whh0 = (const float*)d_in[7];
    const float* bhh0 = (const float*)d_in[8];
    const float* Ahh0 = (const float*)d_in[9];
    const float* Bhh0 = (const float*)d_in[10];
    const float* Wih1 = (const float*)d_in[11];
    const float* bih1 = (const float*)d_in[12];
    const float* Aih1 = (const float*)d_in[13];
    const float* Bih1 = (const float*)d_in[14];
    const float* Whh1 = (const float*)d_in[15];
    const float* bhh1 = (const float*)d_in[16];
    const float* Ahh1 = (const float*)d_in[17];
    const float* Bhh1 = (const float*)d_in[18];
    float* out = (float*)d_out;

    zero_kernel<<<256, 256>>>();
    prep_w_kernel<<<(EMB * NG) / 256, 256>>>(Wih0, Aih0, Bih0, EMB, 0, 0);
    prep_w_kernel<<<(HID * NG) / 256, 256>>>(Wih1, Aih1, Bih1, HID, 0, 1);
    prep_w_kernel<<<(HID * NG) / 256, 256>>>(Whh0, Ahh0, Bhh0, HID, 1, 2);
    prep_w_kernel<<<(HID * NG) / 256, 256>>>(Whh1, Ahh1, Bhh1, HID, 1, 3);
    prep_bias_kernel<<<32, 256>>>(bih0, bhh0, bih1, bhh1);

    // layer 0: input projection (embedding gather fused) + full recurrence (one node)
    gemm_kernel<<<dim3(64, 512), 256>>>(emb, x, EMB, 1);
    recur_kernel<<<NCTA, 256>>>(0, (const int*)0, (float*)0);

    // layer 1: input projection from h0seq + full recurrence (one node)
    gemm_kernel<<<dim3(64, 512), 256>>>(emb, x, HID, 0);
    recur_kernel<<<NCTA, 256>>>(1, lens, out);
}

// round 6
// speedup vs baseline: 2.6189x; 2.6189x over previous
#include <cuda_runtime.h>
#include <cuda_bf16.h>

#define VOCAB 50257
#define EMB   512
#define HID   1024
#define TT    512
#define BB    64
#define NG    4096        // 4*HID
#define LSCALE 2.0f
#define NCTA  128
#define MROWS (TT*BB)     // 32768

// ---------------- static device scratch (no allocation) ----------------
__device__ __align__(128) __nv_bfloat16 g_Wih0hi[NG*EMB], g_Wih0lo[NG*EMB];   // [g][k]
__device__ __align__(128) __nv_bfloat16 g_Wih1hi[NG*HID], g_Wih1lo[NG*HID];   // [g][k]
__device__ __align__(128) __nv_bfloat16 g_Whh0hi[NG*HID], g_Whh0lo[NG*HID];   // [c][k], c=j*4+q
__device__ __align__(128) __nv_bfloat16 g_Whh1hi[NG*HID], g_Whh1lo[NG*HID];
__device__ __align__(128) float g_bsum0[NG], g_bsum1[NG];
__device__ __align__(128) float g_xproj[(size_t)MROWS*NG];                     // fp32 input projections
__device__ __align__(128) __nv_bfloat16 g_x0hi[(size_t)MROWS*EMB], g_x0lo[(size_t)MROWS*EMB];
__device__ __align__(128) __nv_bfloat16 g_h0hi[(size_t)MROWS*HID], g_h0lo[(size_t)MROWS*HID];
__device__ __align__(128) __nv_bfloat16 g_h1hi[2*BB*HID], g_h1lo[2*BB*HID];
__device__ __align__(128) float g_cbuf[2*BB*HID];
__device__ unsigned g_bar_count;
__device__ volatile unsigned g_bar_sense;

// ---------------- PTX helpers ----------------
__device__ __forceinline__ unsigned sptr(const void* p){
    unsigned r;
    asm("{ .reg .u64 t; cvta.to.shared.u64 t, %1; cvt.u32.u64 %0, t; }" : "=r"(r) : "l"(p));
    return r;
}
__device__ __forceinline__ void cpasync16(unsigned d, const void* s){
    asm volatile("cp.async.cg.shared.global [%0], [%1], 16;" :: "r"(d), "l"(s));
}
__device__ __forceinline__ void cpcommit(){ asm volatile("cp.async.commit_group;"); }
__device__ __forceinline__ void cpwait0(){ asm volatile("cp.async.wait_group 0;"); }
__device__ __forceinline__ void ldsm4(unsigned a, unsigned& r0, unsigned& r1, unsigned& r2, unsigned& r3){
    asm volatile("ldmatrix.sync.aligned.m8n8.x4.shared.b16 {%0,%1,%2,%3}, [%4];"
        : "=r"(r0), "=r"(r1), "=r"(r2), "=r"(r3) : "r"(a));
}
__device__ __forceinline__ void mma_bf16(float* c, const unsigned* a, unsigned b0, unsigned b1){
    asm volatile("mma.sync.aligned.m16n8k16.row.col.f32.bf16.bf16.f32 "
        "{%0,%1,%2,%3},{%4,%5,%6,%7},{%8,%9},{%0,%1,%2,%3};"
        : "+f"(c[0]), "+f"(c[1]), "+f"(c[2]), "+f"(c[3])
        : "r"(a[0]), "r"(a[1]), "r"(a[2]), "r"(a[3]), "r"(b0), "r"(b1));
}

// ---------------- prep kernels ----------------
__global__ void bar_reset(){ g_bar_count = 0; g_bar_sense = 0; }

// W_eff = W + LSCALE*B@A, split to bf16 hi/lo, stored [outrow][k] (k contiguous).
// mode 0: outrow = g (gate order, for input projections)
// mode 1: outrow = j*4+q where g = q*HID+j (gate-interleaved, for recurrent weights)
__global__ void prep_w_split(const float* __restrict__ W, const float* __restrict__ A,
                             const float* __restrict__ Bm, int K, int mode, int which){
    int idx = blockIdx.x * blockDim.x + threadIdx.x;
    if (idx >= K * NG) return;
    int g = idx / K, k = idx % K;
    float s = 0.f;
#pragma unroll
    for (int r = 0; r < 8; r++) s += Bm[g*8 + r] * A[r*K + k];
    float v = W[(size_t)g*K + k] + LSCALE * s;
    int oc;
    if (mode == 0) oc = g;
    else { int q = g / HID, j = g % HID; oc = j*4 + q; }
    __nv_bfloat16 hi = __float2bfloat16(v);
    __nv_bfloat16 lo = __float2bfloat16(v - __bfloat162float(hi));
    size_t o = (size_t)oc * K + k;
    switch (which){
        case 0: g_Wih0hi[o] = hi; g_Wih0lo[o] = lo; break;
        case 1: g_Wih1hi[o] = hi; g_Wih1lo[o] = lo; break;
        case 2: g_Whh0hi[o] = hi; g_Whh0lo[o] = lo; break;
        default: g_Whh1hi[o] = hi; g_Whh1lo[o] = lo; break;
    }
}

__global__ void prep_bias_kernel(const float* __restrict__ bih0, const float* __restrict__ bhh0,
                                 const float* __restrict__ bih1, const float* __restrict__ bhh1){
    int i = blockIdx.x * blockDim.x + threadIdx.x;
    if (i < NG)          g_bsum0[i]      = bih0[i] + bhh0[i];
    else if (i < 2*NG)   g_bsum1[i - NG] = bih1[i - NG] + bhh1[i - NG];
}

// gathered embedding rows, split bf16: row = t*64+b, from emb[x[b][t]]
__global__ void gather_x0(const int* __restrict__ x, const float* __restrict__ emb){
    size_t idx = (size_t)blockIdx.x * 256 + threadIdx.x;   // MROWS*EMB total
    int k = (int)(idx & (EMB - 1));
    int row = (int)(idx >> 9);
    int t = row >> 6, b = row & 63;
    int tok = x[b*TT + t];
    float v = emb[(size_t)tok*EMB + k];
    __nv_bfloat16 hi = __float2bfloat16(v);
    g_x0hi[idx] = hi;
    g_x0lo[idx] = __float2bfloat16(v - __bfloat162float(hi));
}

// ---------------- big input-projection GEMM (split-bf16 HMMA) ----------------
// C[M=32768][NG] += A[M][K] @ B[n][K]^T ; CTA tile 64x128, k-stage 32, cp.async double-buffered.
// smem per buffer (30720B): Ahi@0(5120) Alo@5120 Bhi@10240(10240) Blo@20480 ; row stride 40 elems.
__global__ void __launch_bounds__(256, 2)
gemm_hmma(int sel, int K){
    extern __shared__ char smraw[];
    const unsigned smb = sptr(smraw);
    const int tid = threadIdx.x;
    const int wid = tid >> 5, lane = tid & 31;
    const int bm = blockIdx.y * 64;
    const int bn = blockIdx.x * 128;
    const int wm = wid & 3, wn = wid >> 2;

    const __nv_bfloat16 *Ah, *Al, *Bh, *Bl;
    if (sel == 0){ Ah = g_x0hi; Al = g_x0lo; Bh = g_Wih0hi; Bl = g_Wih0lo; }
    else         { Ah = g_h0hi; Al = g_h0lo; Bh = g_Wih1hi; Bl = g_Wih1lo; }

    float c[8][4];
#pragma unroll
    for (int i = 0; i < 8; i++)
#pragma unroll
        for (int j = 0; j < 4; j++) c[i][j] = 0.f;

    const int grp = lane >> 3, lr = lane & 7;
    const int a_r = wm*16 + lr + ((grp & 1) << 3);
    const int a_c = (grp >> 1) << 3;
    const int b_rb = lr + ((grp >> 1) << 3);
    const int b_c = (grp & 1) << 3;

    const int S = K >> 5;
    auto load_stage = [&](int s){
        unsigned buf = smb + (unsigned)((s & 1) * 30720);
        int kt = s << 5;
#pragma unroll
        for (int i = 0; i < 6; i++){
            int cid = tid + (i << 8);
            const __nv_bfloat16* src; unsigned dst;
            if (cid < 512){
                int sp = cid >> 8, rem = cid & 255;
                int row = rem >> 2, kc = (rem & 3) << 3;
                src = (sp ? Al : Ah) + (size_t)(bm + row) * K + kt + kc;
                dst = buf + (unsigned)(sp * 5120 + (row*40 + kc) * 2);
            } else {
                int c2 = cid - 512;
                int sp = c2 >> 9, rem = c2 & 511;
                int row = rem >> 2, kc = (rem & 3) << 3;
                src = (sp ? Bl : Bh) + (size_t)(bn + row) * K + kt + kc;
                dst = buf + (unsigned)(10240 + sp * 10240 + (row*40 + kc) * 2);
            }
            cpasync16(dst, src);
        }
    };

    load_stage(0); cpcommit();
    for (int s = 0; s < S; s++){
        cpwait0(); __syncthreads();
        if (s + 1 < S){ load_stage(s + 1); cpcommit(); }
        unsigned buf = smb + (unsigned)((s & 1) * 30720);
#pragma unroll
        for (int kk = 0; kk < 32; kk += 16){
            unsigned ah[4], al[4];
            ldsm4(buf +         (unsigned)((a_r*40 + kk + a_c) * 2), ah[0], ah[1], ah[2], ah[3]);
            ldsm4(buf + 5120u + (unsigned)((a_r*40 + kk + a_c) * 2), al[0], al[1], al[2], al[3]);
#pragma unroll
            for (int nh = 0; nh < 2; nh++){
                int n0 = wn*64 + nh*32;
                unsigned bh[8], bl[8];
                ldsm4(buf + 10240u + (unsigned)(((n0      + b_rb)*40 + kk + b_c) * 2), bh[0], bh[1], bh[2], bh[3]);
                ldsm4(buf + 10240u + (unsigned)(((n0 + 16 + b_rb)*40 + kk + b_c) * 2), bh[4], bh[5], bh[6], bh[7]);
                ldsm4(buf + 20480u + (unsigned)(((n0      + b_rb)*40 + kk + b_c) * 2), bl[0], bl[1], bl[2], bl[3]);
                ldsm4(buf + 20480u + (unsigned)(((n0 + 16 + b_rb)*40 + kk + b_c) * 2), bl[4], bl[5], bl[6], bl[7]);
#pragma unroll
                for (int f = 0; f < 4; f++){
                    int nf = nh*4 + f;
                    mma_bf16(c[nf], ah, bh[f*2], bh[f*2+1]);
                    mma_bf16(c[nf], ah, bl[f*2], bl[f*2+1]);
                    mma_bf16(c[nf], al, bh[f*2], bh[f*2+1]);
                }
            }
        }
    }
    int r0 = lane >> 2, tc = (lane & 3) << 1;
    int gr = bm + wm*16 + r0;
#pragma unroll
    for (int nf = 0; nf < 8; nf++){
        int col = bn + wn*64 + nf*8 + tc;
        *(float2*)&g_xproj[(size_t)gr * NG + col]       = make_float2(c[nf][0], c[nf][1]);
        *(float2*)&g_xproj[(size_t)(gr + 8) * NG + col] = make_float2(c[nf][2], c[nf][3]);
    }
}

// ---------------- persistent recurrent kernel (split-bf16 HMMA) ----------------
// 128 CTAs; CTA owns 32 gate-interleaved cols (8 hidden units x 4 gates), all 64 batches.
// K-stage 64, cp.async double-buffered; grid barrier between steps.
// smem per buffer (27648B): Ahi@0(9216) Alo@9216 Bhi@18432(4608) Blo@23040 ; row stride 72 elems.
// gate staging tile at 55296: float[64][36].
__global__ void __launch_bounds__(256, 1)
recur_hmma(int layer, const int* __restrict__ lengths, float* __restrict__ fout){
    extern __shared__ char smraw[];
    const unsigned smb = sptr(smraw);
    float* gt = (float*)(smraw + 55296);
    const int tid = threadIdx.x;
    const int wid = tid >> 5, lane = tid & 31;
    const int c0 = blockIdx.x * 32;
    const int wm = wid & 3, wn = wid >> 2;
    const int grp = lane >> 3, lr = lane & 7;
    const int a_r = wm*16 + lr + ((grp & 1) << 3);
    const int a_c = (grp >> 1) << 3;
    const int b_r = wn*16 + lr + ((grp >> 1) << 3);
    const int b_c = (grp & 1) << 3;

    const __nv_bfloat16* __restrict__ Wh = layer ? g_Whh1hi : g_Whh0hi;
    const __nv_bfloat16* __restrict__ Wl = layer ? g_Whh1lo : g_Whh0lo;
    const float* __restrict__ bs = layer ? g_bsum1 : g_bsum0;

    unsigned gen = 0;
    for (int t = 0; t < TT; t++){
        float cfr[2][4] = {{0.f,0.f,0.f,0.f},{0.f,0.f,0.f,0.f}};
        if (t > 0){
            const __nv_bfloat16* ah = layer ? (g_h1hi + (size_t)((t-1) & 1) * (BB*HID))
                                            : (g_h0hi + (size_t)(t-1) * (BB*HID));
            const __nv_bfloat16* al = layer ? (g_h1lo + (size_t)((t-1) & 1) * (BB*HID))
                                            : (g_h0lo + (size_t)(t-1) * (BB*HID));
            auto load_stage = [&](int s){
                unsigned buf = smb + (unsigned)((s & 1) * 27648);
                int kt = s << 6;
#pragma unroll
                for (int i = 0; i < 6; i++){
                    int cid = tid + (i << 8);
                    const __nv_bfloat16* src; unsigned dst;
                    if (cid < 1024){
                        int sp = cid >> 9, rem = cid & 511;
                        int row = rem >> 3, kc = (rem & 7) << 3;
                        src = (sp ? al : ah) + row*HID + kt + kc;
                        dst = buf + (unsigned)(sp * 9216 + (row*72 + kc) * 2);
                    } else {
                        int c2 = cid - 1024;
                        int sp = c2 >> 8, rem = c2 & 255;
                        int row = rem >> 3, kc = (rem & 7) << 3;
                        src = (sp ? Wl : Wh) + (size_t)(c0 + row) * HID + kt + kc;
                        dst = buf + (unsigned)(18432 + sp * 4608 + (row*72 + kc) * 2);
                    }
                    cpasync16(dst, src);
                }
            };
            load_stage(0); cpcommit();
            for (int s = 0; s < 16; s++){
                cpwait0(); __syncthreads();
                if (s < 15){ load_stage(s + 1); cpcommit(); }
                unsigned buf = smb + (unsigned)((s & 1) * 27648);
#pragma unroll
                for (int kk = 0; kk < 64; kk += 16){
                    unsigned ah4[4], al4[4], bh4[4], bl4[4];
                    ldsm4(buf +          (unsigned)((a_r*72 + kk + a_c) * 2), ah4[0], ah4[1], ah4[2], ah4[3]);
                    ldsm4(buf + 9216u  + (unsigned)((a_r*72 + kk + a_c) * 2), al4[0], al4[1], al4[2], al4[3]);
                    ldsm4(buf + 18432u + (unsigned)((b_r*72 + kk + b_c) * 2), bh4[0], bh4[1], bh4[2], bh4[3]);
                    ldsm4(buf + 23040u + (unsigned)((b_r*72 + kk + b_c) * 2), bl4[0], bl4[1], bl4[2], bl4[3]);
                    mma_bf16(cfr[0], ah4, bh4[0], bh4[1]);
                    mma_bf16(cfr[0], ah4, bl4[0], bl4[1]);
                    mma_bf16(cfr[0], al4, bh4[0], bh4[1]);
                    mma_bf16(cfr[1], ah4, bh4[2], bh4[3]);
                    mma_bf16(cfr[1], ah4, bl4[2], bl4[3]);
                    mma_bf16(cfr[1], al4, bh4[2], bh4[3]);
                }
            }
        }
        // stage gate pre-activations to smem
        {
            int r0 = lane >> 2, tc = (lane & 3) << 1;
#pragma unroll
            for (int nf = 0; nf < 2; nf++){
                int col = wn*16 + nf*8 + tc;
                *(float2*)&gt[(wm*16 + r0) * 36 + col]     = make_float2(cfr[nf][0], cfr[nf][1]);
                *(float2*)&gt[(wm*16 + 8 + r0) * 36 + col] = make_float2(cfr[nf][2], cfr[nf][3]);
            }
        }
        __syncthreads();
        const float* __restrict__ xpt = g_xproj + (size_t)t * (BB * NG);
#pragma unroll
        for (int pp = 0; pp < 2; pp++){
            int p = tid + pp * 256;
            int b = p >> 3, jl = p & 7;
            float4 gv = *(float4*)&gt[b*36 + jl*4];
            int j = blockIdx.x * 8 + jl;
            float vi = gv.x + bs[j]           + xpt[b*NG + j];
            float vf = gv.y + bs[HID + j]     + xpt[b*NG + HID + j];
            float vg = gv.z + bs[2*HID + j]   + xpt[b*NG + 2*HID + j];
            float vo = gv.w + bs[3*HID + j]   + xpt[b*NG + 3*HID + j];
            float cp = t ? g_cbuf[((t-1) & 1) * (BB*HID) + b*HID + j] : 0.f;
            float is = 1.f / (1.f + __expf(-vi));
            float fs = 1.f / (1.f + __expf(-vf));
            float gs = tanhf(vg);
            float os = 1.f / (1.f + __expf(-vo));
            float cn = fs * cp + is * gs;
            float hn = os * tanhf(cn);
            g_cbuf[(t & 1) * (BB*HID) + b*HID + j] = cn;
            __nv_bfloat16 hh = __float2bfloat16(hn);
            __nv_bfloat16 hl = __float2bfloat16(hn - __bfloat162float(hh));
            if (layer){
                g_h1hi[(t & 1) * (BB*HID) + b*HID + j] = hh;
                g_h1lo[(t & 1) * (BB*HID) + b*HID + j] = hl;
                if (lengths[b] - 1 == t) fout[b*HID + j] = hn;
            } else {
                g_h0hi[(size_t)t * (BB*HID) + b*HID + j] = hh;
                g_h0lo[(size_t)t * (BB*HID) + b*HID + j] = hl;
            }
        }
        // -------- grid barrier (sense-reversal) --------
        __syncthreads();
        if (tid == 0){
            __threadfence();
            if (atomicAdd(&g_bar_count, 1u) == NCTA - 1){
                atomicExch(&g_bar_count, 0u);
                __threadfence();
                g_bar_sense = gen + 1;
            } else {
                while (g_bar_sense == gen) { }
                __threadfence();
            }
        }
        __syncthreads();
        gen++;
    }
}

// ---------------- host ----------------
extern "C" void kernel_launch(void* const* d_in, const int* in_sizes, int n_in,
                              void* d_out, int out_size) {
    const int*   x    = (const int*)  d_in[0];
    const int*   lens = (const int*)  d_in[1];
    const float* emb  = (const float*)d_in[2];
    const float* Wih0 = (const float*)d_in[3];
    const float* bih0 = (const float*)d_in[4];
    const float* Aih0 = (const float*)d_in[5];
    const float* Bih0 = (const float*)d_in[6];
    const float* Whh0 = (const float*)d_in[7];
    const float* bhh0 = (const float*)d_in[8];
    const float* Ahh0 = (const float*)d_in[9];
    const float* Bhh0 = (const float*)d_in[10];
    const float* Wih1 = (const float*)d_in[11];
    const float* bih1 = (const float*)d_in[12];
    const float* Aih1 = (const float*)d_in[13];
    const float* Bih1 = (const float*)d_in[14];
    const float* Whh1 = (const float*)d_in[15];
    const float* bhh1 = (const float*)d_in[16];
    const float* Ahh1 = (const float*)d_in[17];
    const float* Bhh1 = (const float*)d_in[18];
    float* out = (float*)d_out;

    cudaFuncSetAttribute(gemm_hmma,  cudaFuncAttributeMaxDynamicSharedMemorySize, 61440);
    cudaFuncSetAttribute(recur_hmma, cudaFuncAttributeMaxDynamicSharedMemorySize, 64512);

    bar_reset<<<1, 1>>>();
    prep_bias_kernel<<<32, 256>>>(bih0, bhh0, bih1, bhh1);
    prep_w_split<<<(EMB * NG) / 256, 256>>>(Wih0, Aih0, Bih0, EMB, 0, 0);
    prep_w_split<<<(HID * NG) / 256, 256>>>(Wih1, Aih1, Bih1, HID, 0, 1);
    prep_w_split<<<(HID * NG) / 256, 256>>>(Whh0, Ahh0, Bhh0, HID, 1, 2);
    prep_w_split<<<(HID * NG) / 256, 256>>>(Whh1, Ahh1, Bhh1, HID, 1, 3);
    gather_x0<<<(MROWS * EMB) / 256, 256>>>(x, emb);

    // layer 0: input projection + full recurrence
    gemm_hmma<<<dim3(32, 512), 256, 61440>>>(0, EMB);
    recur_hmma<<<NCTA, 256, 64512>>>(0, (const int*)0, (float*)0);

    // layer 1: input projection from h0 + full recurrence
    bar_reset<<<1, 1>>>();
    gemm_hmma<<<dim3(32, 512), 256, 61440>>>(1, HID);
    recur_hmma<<<NCTA, 256, 64512>>>(1, lens, out);
}

// round 7
// speedup vs baseline: 3.0698x; 1.1722x over previous
#include <cuda_runtime.h>
#include <cuda_bf16.h>

#define VOCAB 50257
#define EMB   512
#define HID   1024
#define TT    512
#define BB    64
#define NG    4096        // 4*HID
#define LSCALE 2.0f
#define NCTA  128
#define MROWS (TT*BB)     // 32768

// ---------------- static device scratch (no allocation) ----------------
__device__ __align__(128) __nv_bfloat16 g_Wih0hi[NG*EMB], g_Wih0lo[NG*EMB];   // [g][k]
__device__ __align__(128) __nv_bfloat16 g_Wih1hi[NG*HID], g_Wih1lo[NG*HID];   // [g][k]
__device__ __align__(128) __nv_bfloat16 g_Whh0hi[NG*HID], g_Whh0lo[NG*HID];   // [c][k], c=j*4+q
__device__ __align__(128) __nv_bfloat16 g_Whh1hi[NG*HID], g_Whh1lo[NG*HID];
__device__ __align__(128) float g_bsum0[NG], g_bsum1[NG];
__device__ __align__(128) float g_xproj[(size_t)MROWS*NG];                     // fp32 input projections
__device__ __align__(128) __nv_bfloat16 g_x0hi[(size_t)MROWS*EMB], g_x0lo[(size_t)MROWS*EMB];
__device__ __align__(128) __nv_bfloat16 g_h0hi[(size_t)MROWS*HID], g_h0lo[(size_t)MROWS*HID];
__device__ __align__(128) __nv_bfloat16 g_h1hi[2*BB*HID], g_h1lo[2*BB*HID];
__device__ __align__(128) float g_cbuf[2*BB*HID];
__device__ unsigned g_bar_count;
__device__ volatile unsigned g_bar_sense;

// ---------------- PTX helpers ----------------
__device__ __forceinline__ unsigned sptr(const void* p){
    unsigned r;
    asm("{ .reg .u64 t; cvta.to.shared.u64 t, %1; cvt.u32.u64 %0, t; }" : "=r"(r) : "l"(p));
    return r;
}
__device__ __forceinline__ void cpasync16(unsigned d, const void* s){
    asm volatile("cp.async.cg.shared.global [%0], [%1], 16;" :: "r"(d), "l"(s));
}
__device__ __forceinline__ void cpcommit(){ asm volatile("cp.async.commit_group;"); }
__device__ __forceinline__ void cpwait0(){ asm volatile("cp.async.wait_group 0;"); }
__device__ __forceinline__ void cpwait2(){ asm volatile("cp.async.wait_group 2;"); }
__device__ __forceinline__ void ldsm4(unsigned a, unsigned& r0, unsigned& r1, unsigned& r2, unsigned& r3){
    asm volatile("ldmatrix.sync.aligned.m8n8.x4.shared.b16 {%0,%1,%2,%3}, [%4];"
        : "=r"(r0), "=r"(r1), "=r"(r2), "=r"(r3) : "r"(a));
}
__device__ __forceinline__ void mma_bf16(float* c, const unsigned* a, unsigned b0, unsigned b1){
    asm volatile("mma.sync.aligned.m16n8k16.row.col.f32.bf16.bf16.f32 "
        "{%0,%1,%2,%3},{%4,%5,%6,%7},{%8,%9},{%0,%1,%2,%3};"
        : "+f"(c[0]), "+f"(c[1]), "+f"(c[2]), "+f"(c[3])
        : "r"(a[0]), "r"(a[1]), "r"(a[2]), "r"(a[3]), "r"(b0), "r"(b1));
}

// ---------------- prep kernels ----------------
__global__ void bar_reset(){ g_bar_count = 0; g_bar_sense = 0; }

__global__ void prep_w_split(const float* __restrict__ W, const float* __restrict__ A,
                             const float* __restrict__ Bm, int K, int mode, int which){
    int idx = blockIdx.x * blockDim.x + threadIdx.x;
    if (idx >= K * NG) return;
    int g = idx / K, k = idx % K;
    float s = 0.f;
#pragma unroll
    for (int r = 0; r < 8; r++) s += Bm[g*8 + r] * A[r*K + k];
    float v = W[(size_t)g*K + k] + LSCALE * s;
    int oc;
    if (mode == 0) oc = g;
    else { int q = g / HID, j = g % HID; oc = j*4 + q; }
    __nv_bfloat16 hi = __float2bfloat16(v);
    __nv_bfloat16 lo = __float2bfloat16(v - __bfloat162float(hi));
    size_t o = (size_t)oc * K + k;
    switch (which){
        case 0: g_Wih0hi[o] = hi; g_Wih0lo[o] = lo; break;
        case 1: g_Wih1hi[o] = hi; g_Wih1lo[o] = lo; break;
        case 2: g_Whh0hi[o] = hi; g_Whh0lo[o] = lo; break;
        default: g_Whh1hi[o] = hi; g_Whh1lo[o] = lo; break;
    }
}

__global__ void prep_bias_kernel(const float* __restrict__ bih0, const float* __restrict__ bhh0,
                                 const float* __restrict__ bih1, const float* __restrict__ bhh1){
    int i = blockIdx.x * blockDim.x + threadIdx.x;
    if (i < NG)          g_bsum0[i]      = bih0[i] + bhh0[i];
    else if (i < 2*NG)   g_bsum1[i - NG] = bih1[i - NG] + bhh1[i - NG];
}

__global__ void gather_x0(const int* __restrict__ x, const float* __restrict__ emb){
    size_t idx = (size_t)blockIdx.x * 256 + threadIdx.x;
    int k = (int)(idx & (EMB - 1));
    int row = (int)(idx >> 9);
    int t = row >> 6, b = row & 63;
    int tok = x[b*TT + t];
    float v = emb[(size_t)tok*EMB + k];
    __nv_bfloat16 hi = __float2bfloat16(v);
    g_x0hi[idx] = hi;
    g_x0lo[idx] = __float2bfloat16(v - __bfloat162float(hi));
}

// ---------------- big input-projection GEMM (split-bf16 HMMA) ----------------
__global__ void __launch_bounds__(256, 2)
gemm_hmma(int sel, int K){
    extern __shared__ char smraw[];
    const unsigned smb = sptr(smraw);
    const int tid = threadIdx.x;
    const int wid = tid >> 5, lane = tid & 31;
    const int bm = blockIdx.y * 64;
    const int bn = blockIdx.x * 128;
    const int wm = wid & 3, wn = wid >> 2;

    const __nv_bfloat16 *Ah, *Al, *Bh, *Bl;
    if (sel == 0){ Ah = g_x0hi; Al = g_x0lo; Bh = g_Wih0hi; Bl = g_Wih0lo; }
    else         { Ah = g_h0hi; Al = g_h0lo; Bh = g_Wih1hi; Bl = g_Wih1lo; }

    float c[8][4];
#pragma unroll
    for (int i = 0; i < 8; i++)
#pragma unroll
        for (int j = 0; j < 4; j++) c[i][j] = 0.f;

    const int grp = lane >> 3, lr = lane & 7;
    const int a_r = wm*16 + lr + ((grp & 1) << 3);
    const int a_c = (grp >> 1) << 3;
    const int b_rb = lr + ((grp >> 1) << 3);
    const int b_c = (grp & 1) << 3;

    const int S = K >> 5;
    auto load_stage = [&](int s){
        unsigned buf = smb + (unsigned)((s & 1) * 30720);
        int kt = s << 5;
#pragma unroll
        for (int i = 0; i < 6; i++){
            int cid = tid + (i << 8);
            const __nv_bfloat16* src; unsigned dst;
            if (cid < 512){
                int sp = cid >> 8, rem = cid & 255;
                int row = rem >> 2, kc = (rem & 3) << 3;
                src = (sp ? Al : Ah) + (size_t)(bm + row) * K + kt + kc;
                dst = buf + (unsigned)(sp * 5120 + (row*40 + kc) * 2);
            } else {
                int c2 = cid - 512;
                int sp = c2 >> 9, rem = c2 & 511;
                int row = rem >> 2, kc = (rem & 3) << 3;
                src = (sp ? Bl : Bh) + (size_t)(bn + row) * K + kt + kc;
                dst = buf + (unsigned)(10240 + sp * 10240 + (row*40 + kc) * 2);
            }
            cpasync16(dst, src);
        }
    };

    load_stage(0); cpcommit();
    for (int s = 0; s < S; s++){
        cpwait0(); __syncthreads();
        if (s + 1 < S){ load_stage(s + 1); cpcommit(); }
        unsigned buf = smb + (unsigned)((s & 1) * 30720);
#pragma unroll
        for (int kk = 0; kk < 32; kk += 16){
            unsigned ah[4], al[4];
            ldsm4(buf +         (unsigned)((a_r*40 + kk + a_c) * 2), ah[0], ah[1], ah[2], ah[3]);
            ldsm4(buf + 5120u + (unsigned)((a_r*40 + kk + a_c) * 2), al[0], al[1], al[2], al[3]);
#pragma unroll
            for (int nh = 0; nh < 2; nh++){
                int n0 = wn*64 + nh*32;
                unsigned bh[8], bl[8];
                ldsm4(buf + 10240u + (unsigned)(((n0      + b_rb)*40 + kk + b_c) * 2), bh[0], bh[1], bh[2], bh[3]);
                ldsm4(buf + 10240u + (unsigned)(((n0 + 16 + b_rb)*40 + kk + b_c) * 2), bh[4], bh[5], bh[6], bh[7]);
                ldsm4(buf + 20480u + (unsigned)(((n0      + b_rb)*40 + kk + b_c) * 2), bl[0], bl[1], bl[2], bl[3]);
                ldsm4(buf + 20480u + (unsigned)(((n0 + 16 + b_rb)*40 + kk + b_c) * 2), bl[4], bl[5], bl[6], bl[7]);
#pragma unroll
                for (int f = 0; f < 4; f++){
                    int nf = nh*4 + f;
                    mma_bf16(c[nf], ah, bh[f*2], bh[f*2+1]);
                    mma_bf16(c[nf], ah, bl[f*2], bl[f*2+1]);
                    mma_bf16(c[nf], al, bh[f*2], bh[f*2+1]);
                }
            }
        }
    }
    int r0 = lane >> 2, tc = (lane & 3) << 1;
    int gr = bm + wm*16 + r0;
#pragma unroll
    for (int nf = 0; nf < 8; nf++){
        int col = bn + wn*64 + nf*8 + tc;
        *(float2*)&g_xproj[(size_t)gr * NG + col]       = make_float2(c[nf][0], c[nf][1]);
        *(float2*)&g_xproj[(size_t)(gr + 8) * NG + col] = make_float2(c[nf][2], c[nf][3]);
    }
}

// ---------------- persistent recurrent kernel: weights resident in SMEM ----------------
// smem layout (dynamic, 230400 B total):
//   [0..73728)        W hi: 16 stage tiles of 4608 B   (32 rows x 64 k, row stride 72)
//   [73728..147456)   W lo: same
//   [147456..221184)  h ring: 4 bufs x 18432 (hi 9216 + lo 9216), row stride 72
//   [221184..230400)  gate tile float[64][36]
#define WLO_OFF 73728u
#define HR_OFF  147456u
#define GT_OFF  221184u
__global__ void __launch_bounds__(256, 1)
recur_hmma(int layer, const int* __restrict__ lengths, float* __restrict__ fout){
    extern __shared__ char smraw[];
    const unsigned smb = sptr(smraw);
    float* gt = (float*)(smraw + GT_OFF);
    const int tid = threadIdx.x;
    const int wid = tid >> 5, lane = tid & 31;
    const int c0 = blockIdx.x * 32;
    const int wm = wid & 3, wn = wid >> 2;
    const int grp = lane >> 3, lr = lane & 7;
    const int a_r = wm*16 + lr + ((grp & 1) << 3);
    const int a_c = (grp >> 1) << 3;
    const int b_r = wn*16 + lr + ((grp >> 1) << 3);
    const int b_c = (grp & 1) << 3;

    const __nv_bfloat16* __restrict__ Wh = layer ? g_Whh1hi : g_Whh0hi;
    const __nv_bfloat16* __restrict__ Wl = layer ? g_Whh1lo : g_Whh0lo;
    const float* __restrict__ bs = layer ? g_bsum1 : g_bsum0;

    // ---- one-time weight preload: 2 splits x 16 stages x 32 rows x 64 k ----
    for (int it = 0; it < 32; it++){
        int cid = it * 256 + tid;                // 8192 chunks of 16B
        int sp = cid >> 12;
        int rem = cid & 4095;
        int stg = rem >> 8;
        int r2 = rem & 255;
        int row = r2 >> 3, kc = (r2 & 7) << 3;
        const __nv_bfloat16* src = (sp ? Wl : Wh) + (size_t)(c0 + row) * HID + stg*64 + kc;
        unsigned dst = smb + (unsigned)(sp * 73728 + stg * 4608 + (row*72 + kc) * 2);
        cpasync16(dst, src);
    }
    cpcommit(); cpwait0(); __syncthreads();

    // epilogue index mapping (2 points per thread)
    const int jl0 = tid & 7, b_0 = tid >> 3;
    const int jglob = blockIdx.x * 8 + jl0;

    unsigned gen = 0;
    for (int t = 0; t < TT; t++){
        const float* __restrict__ xpt = g_xproj + (size_t)t * (BB * NG);
        // ---- prefetch epilogue operands (independent of GEMM) ----
        float pxi[2], pxf[2], pxg[2], pxo[2], pcp[2];
#pragma unroll
        for (int pp = 0; pp < 2; pp++){
            int b = b_0 + pp * 32;
            pxi[pp] = xpt[b*NG + jglob];
            pxf[pp] = xpt[b*NG + HID + jglob];
            pxg[pp] = xpt[b*NG + 2*HID + jglob];
            pxo[pp] = xpt[b*NG + 3*HID + jglob];
            pcp[pp] = t ? g_cbuf[((t-1) & 1) * (BB*HID) + b*HID + jglob] : 0.f;
        }

        float cfr[2][4] = {{0.f,0.f,0.f,0.f},{0.f,0.f,0.f,0.f}};
        if (t > 0){
            const __nv_bfloat16* ah = layer ? (g_h1hi + (size_t)((t-1) & 1) * (BB*HID))
                                            : (g_h0hi + (size_t)(t-1) * (BB*HID));
            const __nv_bfloat16* al = layer ? (g_h1lo + (size_t)((t-1) & 1) * (BB*HID))
                                            : (g_h0lo + (size_t)(t-1) * (BB*HID));
            auto load_h = [&](int s){
                unsigned buf = smb + HR_OFF + (unsigned)((s & 3) * 18432);
                int kt = s << 6;
#pragma unroll
                for (int i = 0; i < 4; i++){
                    int cid = tid + (i << 8);         // 1024 chunks: hi 512 + lo 512
                    int sp = cid >> 9, rem = cid & 511;
                    int row = rem >> 3, kc = (rem & 7) << 3;
                    const __nv_bfloat16* src = (sp ? al : ah) + row*HID + kt + kc;
                    unsigned dst = buf + (unsigned)(sp * 9216 + (row*72 + kc) * 2);
                    cpasync16(dst, src);
                }
            };
            load_h(0); cpcommit();
            load_h(1); cpcommit();
            load_h(2); cpcommit();
#pragma unroll 1
            for (int s = 0; s < 16; s++){
                cpwait2();
                __syncthreads();
                if (s + 3 < 16) load_h(s + 3);
                cpcommit();
                unsigned wbh = smb + (unsigned)(s * 4608);
                unsigned wbl = wbh + WLO_OFF;
                unsigned hbh = smb + HR_OFF + (unsigned)((s & 3) * 18432);
                unsigned hbl = hbh + 9216u;
#pragma unroll
                for (int kk = 0; kk < 64; kk += 16){
                    unsigned ah4[4], al4[4], bh4[4], bl4[4];
                    ldsm4(hbh + (unsigned)((a_r*72 + kk + a_c) * 2), ah4[0], ah4[1], ah4[2], ah4[3]);
                    ldsm4(hbl + (unsigned)((a_r*72 + kk + a_c) * 2), al4[0], al4[1], al4[2], al4[3]);
                    ldsm4(wbh + (unsigned)((b_r*72 + kk + b_c) * 2), bh4[0], bh4[1], bh4[2], bh4[3]);
                    ldsm4(wbl + (unsigned)((b_r*72 + kk + b_c) * 2), bl4[0], bl4[1], bl4[2], bl4[3]);
                    mma_bf16(cfr[0], ah4, bh4[0], bh4[1]);
                    mma_bf16(cfr[0], ah4, bl4[0], bl4[1]);
                    mma_bf16(cfr[0], al4, bh4[0], bh4[1]);
                    mma_bf16(cfr[1], ah4, bh4[2], bh4[3]);
                    mma_bf16(cfr[1], ah4, bl4[2], bl4[3]);
                    mma_bf16(cfr[1], al4, bh4[2], bh4[3]);
                }
            }
        }
        // stage gate pre-activations to smem
        {
            int r0 = lane >> 2, tc = (lane & 3) << 1;
#pragma unroll
            for (int nf = 0; nf < 2; nf++){
                int col = wn*16 + nf*8 + tc;
                *(float2*)&gt[(wm*16 + r0) * 36 + col]     = make_float2(cfr[nf][0], cfr[nf][1]);
                *(float2*)&gt[(wm*16 + 8 + r0) * 36 + col] = make_float2(cfr[nf][2], cfr[nf][3]);
            }
        }
        __syncthreads();
#pragma unroll
        for (int pp = 0; pp < 2; pp++){
            int b = b_0 + pp * 32;
            float4 gv = *(float4*)&gt[b*36 + jl0*4];
            float vi = gv.x + bs[jglob]           + pxi[pp];
            float vf = gv.y + bs[HID + jglob]     + pxf[pp];
            float vg = gv.z + bs[2*HID + jglob]   + pxg[pp];
            float vo = gv.w + bs[3*HID + jglob]   + pxo[pp];
            float is = 1.f / (1.f + __expf(-vi));
            float fs = 1.f / (1.f + __expf(-vf));
            float gs = tanhf(vg);
            float os = 1.f / (1.f + __expf(-vo));
            float cn = fs * pcp[pp] + is * gs;
            float hn = os * tanhf(cn);
            g_cbuf[(t & 1) * (BB*HID) + b*HID + jglob] = cn;
            __nv_bfloat16 hh = __float2bfloat16(hn);
            __nv_bfloat16 hl = __float2bfloat16(hn - __bfloat162float(hh));
            if (layer){
                g_h1hi[(t & 1) * (BB*HID) + b*HID + jglob] = hh;
                g_h1lo[(t & 1) * (BB*HID) + b*HID + jglob] = hl;
                if (lengths[b] - 1 == t) fout[b*HID + jglob] = hn;
            } else {
                g_h0hi[(size_t)t * (BB*HID) + b*HID + jglob] = hh;
                g_h0lo[(size_t)t * (BB*HID) + b*HID + jglob] = hl;
            }
        }
        // -------- grid barrier (sense-reversal) --------
        __syncthreads();
        if (tid == 0){
            __threadfence();
            if (atomicAdd(&g_bar_count, 1u) == NCTA - 1){
                atomicExch(&g_bar_count, 0u);
                __threadfence();
                g_bar_sense = gen + 1;
            } else {
                while (g_bar_sense == gen) { }
                __threadfence();
            }
        }
        __syncthreads();
        gen++;
    }
}

// ---------------- host ----------------
extern "C" void kernel_launch(void* const* d_in, const int* in_sizes, int n_in,
                              void* d_out, int out_size) {
    const int*   x    = (const int*)  d_in[0];
    const int*   lens = (const int*)  d_in[1];
    const float* emb  = (const float*)d_in[2];
    const float* Wih0 = (const float*)d_in[3];
    const float* bih0 = (const float*)d_in[4];
    const float* Aih0 = (const float*)d_in[5];
    const float* Bih0 = (const float*)d_in[6];
    const float* Whh0 = (const float*)d_in[7];
    const float* bhh0 = (const float*)d_in[8];
    const float* Ahh0 = (const float*)d_in[9];
    const float* Bhh0 = (const float*)d_in[10];
    const float* Wih1 = (const float*)d_in[11];
    const float* bih1 = (const float*)d_in[12];
    const float* Aih1 = (const float*)d_in[13];
    const float* Bih1 = (const float*)d_in[14];
    const float* Whh1 = (const float*)d_in[15];
    const float* bhh1 = (const float*)d_in[16];
    const float* Ahh1 = (const float*)d_in[17];
    const float* Bhh1 = (const float*)d_in[18];
    float* out = (float*)d_out;

    cudaFuncSetAttribute(gemm_hmma,  cudaFuncAttributeMaxDynamicSharedMemorySize, 61440);
    cudaFuncSetAttribute(recur_hmma, cudaFuncAttributeMaxDynamicSharedMemorySize, 230400);

    bar_reset<<<1, 1>>>();
    prep_bias_kernel<<<32, 256>>>(bih0, bhh0, bih1, bhh1);
    prep_w_split<<<(EMB * NG) / 256, 256>>>(Wih0, Aih0, Bih0, EMB, 0, 0);
    prep_w_split<<<(HID * NG) / 256, 256>>>(Wih1, Aih1, Bih1, HID, 0, 1);
    prep_w_split<<<(HID * NG) / 256, 256>>>(Whh0, Ahh0, Bhh0, HID, 1, 2);
    prep_w_split<<<(HID * NG) / 256, 256>>>(Whh1, Ahh1, Bhh1, HID, 1, 3);
    gather_x0<<<(MROWS * EMB) / 256, 256>>>(x, emb);

    // layer 0: input projection + full recurrence
    gemm_hmma<<<dim3(32, 512), 256, 61440>>>(0, EMB);
    recur_hmma<<<NCTA, 256, 230400>>>(0, (const int*)0, (float*)0);

    // layer 1: input projection from h0 + full recurrence
    bar_reset<<<1, 1>>>();
    gemm_hmma<<<dim3(32, 512), 256, 61440>>>(1, HID);
    recur_hmma<<<NCTA, 256, 230400>>>(1, lens, out);
}

// round 8
// speedup vs baseline: 3.1175x; 1.0155x over previous
#include <cuda_runtime.h>
#include <cuda_bf16.h>

#define VOCAB 50257
#define EMB   512
#define HID   1024
#define TT    512
#define BB    64
#define NG    4096        // 4*HID
#define LSCALE 2.0f
#define NCTA  128
#define MROWS (TT*BB)     // 32768
#define NGRP  8
#define GRPSZ (NCTA/NGRP) // 16

// ---------------- static device scratch (no allocation) ----------------
__device__ __align__(128) __nv_bfloat16 g_Wih0hi[NG*EMB], g_Wih0lo[NG*EMB];   // [g][k]
__device__ __align__(128) __nv_bfloat16 g_Wih1hi[NG*HID], g_Wih1lo[NG*HID];   // [g][k]
__device__ __align__(128) __nv_bfloat16 g_Whh0hi[NG*HID], g_Whh0lo[NG*HID];   // [c][k], c=j*4+q
__device__ __align__(128) __nv_bfloat16 g_Whh1hi[NG*HID], g_Whh1lo[NG*HID];
__device__ __align__(128) float g_bsum0[NG], g_bsum1[NG];
__device__ __align__(128) float g_xproj[(size_t)MROWS*NG];                     // fp32 input projections
__device__ __align__(128) __nv_bfloat16 g_x0hi[(size_t)MROWS*EMB], g_x0lo[(size_t)MROWS*EMB];
__device__ __align__(128) __nv_bfloat16 g_h0hi[(size_t)MROWS*HID], g_h0lo[(size_t)MROWS*HID];
__device__ __align__(128) __nv_bfloat16 g_h1hi[2*BB*HID], g_h1lo[2*BB*HID];
__device__ __align__(128) float g_cbuf[2*BB*HID];

// two-level grid barrier (counters spread 256B apart to hit distinct LTS slices)
__device__ __align__(128) unsigned g_cnt[NGRP*64];
__device__ unsigned g_root;
__device__ volatile unsigned g_sense;

// ---------------- PTX helpers ----------------
__device__ __forceinline__ unsigned sptr(const void* p){
    unsigned r;
    asm("{ .reg .u64 t; cvta.to.shared.u64 t, %1; cvt.u32.u64 %0, t; }" : "=r"(r) : "l"(p));
    return r;
}
__device__ __forceinline__ void cpasync16(unsigned d, const void* s){
    asm volatile("cp.async.cg.shared.global [%0], [%1], 16;" :: "r"(d), "l"(s));
}
__device__ __forceinline__ void cpcommit(){ asm volatile("cp.async.commit_group;"); }
__device__ __forceinline__ void cpwait0(){ asm volatile("cp.async.wait_group 0;"); }
__device__ __forceinline__ void cpwait2(){ asm volatile("cp.async.wait_group 2;"); }
__device__ __forceinline__ void ldsm4(unsigned a, unsigned& r0, unsigned& r1, unsigned& r2, unsigned& r3){
    asm volatile("ldmatrix.sync.aligned.m8n8.x4.shared.b16 {%0,%1,%2,%3}, [%4];"
        : "=r"(r0), "=r"(r1), "=r"(r2), "=r"(r3) : "r"(a));
}
__device__ __forceinline__ void mma_bf16(float* c, const unsigned* a, unsigned b0, unsigned b1){
    asm volatile("mma.sync.aligned.m16n8k16.row.col.f32.bf16.bf16.f32 "
        "{%0,%1,%2,%3},{%4,%5,%6,%7},{%8,%9},{%0,%1,%2,%3};"
        : "+f"(c[0]), "+f"(c[1]), "+f"(c[2]), "+f"(c[3])
        : "r"(a[0]), "r"(a[1]), "r"(a[2]), "r"(a[3]), "r"(b0), "r"(b1));
}

// ---------------- prep kernels ----------------
__global__ void bar_reset(){
    if (threadIdx.x < NGRP) g_cnt[threadIdx.x * 64] = 0;
    if (threadIdx.x == 0){ g_root = 0; g_sense = 0; }
}

// All four weight preps fused: W_eff = W + LSCALE*B@A, split bf16 hi/lo.
// mode 0: outrow = g; mode 1: outrow = j*4+q where g = q*HID+j.
__global__ void prep_w_all(
    const float* __restrict__ W0, const float* __restrict__ A0, const float* __restrict__ B0,
    const float* __restrict__ W1, const float* __restrict__ A1, const float* __restrict__ B1,
    const float* __restrict__ W2, const float* __restrict__ A2, const float* __restrict__ B2,
    const float* __restrict__ W3, const float* __restrict__ A3, const float* __restrict__ B3)
{
    int idx = blockIdx.x * blockDim.x + threadIdx.x;
    const int N0 = EMB * NG, N1 = HID * NG;
    const float *W, *A, *Bm; int K, mode, li;
    __nv_bfloat16 *oh, *ol;
    if (idx < N0)            { W=W0; A=A0; Bm=B0; K=EMB; mode=0; oh=g_Wih0hi; ol=g_Wih0lo; li=idx; }
    else if (idx < N0+N1)    { W=W1; A=A1; Bm=B1; K=HID; mode=0; oh=g_Wih1hi; ol=g_Wih1lo; li=idx-N0; }
    else if (idx < N0+2*N1)  { W=W2; A=A2; Bm=B2; K=HID; mode=1; oh=g_Whh0hi; ol=g_Whh0lo; li=idx-N0-N1; }
    else                     { W=W3; A=A3; Bm=B3; K=HID; mode=1; oh=g_Whh1hi; ol=g_Whh1lo; li=idx-N0-2*N1; }
    int g = li / K, k = li % K;
    float s = 0.f;
#pragma unroll
    for (int r = 0; r < 8; r++) s += Bm[g*8 + r] * A[r*K + k];
    float v = W[(size_t)g*K + k] + LSCALE * s;
    int oc;
    if (mode == 0) oc = g;
    else { int q = g / HID, j = g % HID; oc = j*4 + q; }
    __nv_bfloat16 hi = __float2bfloat16(v);
    __nv_bfloat16 lo = __float2bfloat16(v - __bfloat162float(hi));
    size_t o = (size_t)oc * K + k;
    oh[o] = hi; ol[o] = lo;
}

__global__ void prep_bias_kernel(const float* __restrict__ bih0, const float* __restrict__ bhh0,
                                 const float* __restrict__ bih1, const float* __restrict__ bhh1){
    int i = blockIdx.x * blockDim.x + threadIdx.x;
    if (i < NG)          g_bsum0[i]      = bih0[i] + bhh0[i];
    else if (i < 2*NG)   g_bsum1[i - NG] = bih1[i - NG] + bhh1[i - NG];
}

__global__ void gather_x0(const int* __restrict__ x, const float* __restrict__ emb){
    size_t idx = (size_t)blockIdx.x * 256 + threadIdx.x;
    int k = (int)(idx & (EMB - 1));
    int row = (int)(idx >> 9);
    int t = row >> 6, b = row & 63;
    int tok = x[b*TT + t];
    float v = emb[(size_t)tok*EMB + k];
    __nv_bfloat16 hi = __float2bfloat16(v);
    g_x0hi[idx] = hi;
    g_x0lo[idx] = __float2bfloat16(v - __bfloat162float(hi));
}

// ---------------- big input-projection GEMM (split-bf16 HMMA) ----------------
__global__ void __launch_bounds__(256, 2)
gemm_hmma(int sel, int K){
    extern __shared__ char smraw[];
    const unsigned smb = sptr(smraw);
    const int tid = threadIdx.x;
    const int wid = tid >> 5, lane = tid & 31;
    const int bm = blockIdx.y * 64;
    const int bn = blockIdx.x * 128;
    const int wm = wid & 3, wn = wid >> 2;

    const __nv_bfloat16 *Ah, *Al, *Bh, *Bl;
    if (sel == 0){ Ah = g_x0hi; Al = g_x0lo; Bh = g_Wih0hi; Bl = g_Wih0lo; }
    else         { Ah = g_h0hi; Al = g_h0lo; Bh = g_Wih1hi; Bl = g_Wih1lo; }

    float c[8][4];
#pragma unroll
    for (int i = 0; i < 8; i++)
#pragma unroll
        for (int j = 0; j < 4; j++) c[i][j] = 0.f;

    const int grp = lane >> 3, lr = lane & 7;
    const int a_r = wm*16 + lr + ((grp & 1) << 3);
    const int a_c = (grp >> 1) << 3;
    const int b_rb = lr + ((grp >> 1) << 3);
    const int b_c = (grp & 1) << 3;

    const int S = K >> 5;
    auto load_stage = [&](int s){
        unsigned buf = smb + (unsigned)((s & 1) * 30720);
        int kt = s << 5;
#pragma unroll
        for (int i = 0; i < 6; i++){
            int cid = tid + (i << 8);
            const __nv_bfloat16* src; unsigned dst;
            if (cid < 512){
                int sp = cid >> 8, rem = cid & 255;
                int row = rem >> 2, kc = (rem & 3) << 3;
                src = (sp ? Al : Ah) + (size_t)(bm + row) * K + kt + kc;
                dst = buf + (unsigned)(sp * 5120 + (row*40 + kc) * 2);
            } else {
                int c2 = cid - 512;
                int sp = c2 >> 9, rem = c2 & 511;
                int row = rem >> 2, kc = (rem & 3) << 3;
                src = (sp ? Bl : Bh) + (size_t)(bn + row) * K + kt + kc;
                dst = buf + (unsigned)(10240 + sp * 10240 + (row*40 + kc) * 2);
            }
            cpasync16(dst, src);
        }
    };

    load_stage(0); cpcommit();
    for (int s = 0; s < S; s++){
        cpwait0(); __syncthreads();
        if (s + 1 < S){ load_stage(s + 1); cpcommit(); }
        unsigned buf = smb + (unsigned)((s & 1) * 30720);
#pragma unroll
        for (int kk = 0; kk < 32; kk += 16){
            unsigned ah[4], al[4];
            ldsm4(buf +         (unsigned)((a_r*40 + kk + a_c) * 2), ah[0], ah[1], ah[2], ah[3]);
            ldsm4(buf + 5120u + (unsigned)((a_r*40 + kk + a_c) * 2), al[0], al[1], al[2], al[3]);
#pragma unroll
            for (int nh = 0; nh < 2; nh++){
                int n0 = wn*64 + nh*32;
                unsigned bh[8], bl[8];
                ldsm4(buf + 10240u + (unsigned)(((n0      + b_rb)*40 + kk + b_c) * 2), bh[0], bh[1], bh[2], bh[3]);
                ldsm4(buf + 10240u + (unsigned)(((n0 + 16 + b_rb)*40 + kk + b_c) * 2), bh[4], bh[5], bh[6], bh[7]);
                ldsm4(buf + 20480u + (unsigned)(((n0      + b_rb)*40 + kk + b_c) * 2), bl[0], bl[1], bl[2], bl[3]);
                ldsm4(buf + 20480u + (unsigned)(((n0 + 16 + b_rb)*40 + kk + b_c) * 2), bl[4], bl[5], bl[6], bl[7]);
#pragma unroll
                for (int f = 0; f < 4; f++){
                    int nf = nh*4 + f;
                    mma_bf16(c[nf], ah, bh[f*2], bh[f*2+1]);
                    mma_bf16(c[nf], ah, bl[f*2], bl[f*2+1]);
                    mma_bf16(c[nf], al, bh[f*2], bh[f*2+1]);
                }
            }
        }
    }
    int r0 = lane >> 2, tc = (lane & 3) << 1;
    int gr = bm + wm*16 + r0;
#pragma unroll
    for (int nf = 0; nf < 8; nf++){
        int col = bn + wn*64 + nf*8 + tc;
        *(float2*)&g_xproj[(size_t)gr * NG + col]       = make_float2(c[nf][0], c[nf][1]);
        *(float2*)&g_xproj[(size_t)(gr + 8) * NG + col] = make_float2(c[nf][2], c[nf][3]);
    }
}

// ---------------- persistent recurrent kernel: weights resident in SMEM ----------------
// smem layout (dynamic, 230400 B total):
//   [0..73728)        W hi: 16 stage tiles of 4608 B   (32 rows x 64 k, row stride 72)
//   [73728..147456)   W lo: same
//   [147456..221184)  h ring: 4 bufs x 18432 (hi 9216 + lo 9216), row stride 72
//   [221184..230400)  gate tile float[64][36]
#define WLO_OFF 73728u
#define HR_OFF  147456u
#define GT_OFF  221184u
__global__ void __launch_bounds__(256, 1)
recur_hmma(int layer, const int* __restrict__ lengths, float* __restrict__ fout){
    extern __shared__ char smraw[];
    const unsigned smb = sptr(smraw);
    float* gt = (float*)(smraw + GT_OFF);
    const int tid = threadIdx.x;
    const int wid = tid >> 5, lane = tid & 31;
    const int c0 = blockIdx.x * 32;
    const int wm = wid & 3, wn = wid >> 2;
    const int grp = lane >> 3, lr = lane & 7;
    const int a_r = wm*16 + lr + ((grp & 1) << 3);
    const int a_c = (grp >> 1) << 3;
    const int b_r = wn*16 + lr + ((grp >> 1) << 3);
    const int b_c = (grp & 1) << 3;

    const __nv_bfloat16* __restrict__ Wh = layer ? g_Whh1hi : g_Whh0hi;
    const __nv_bfloat16* __restrict__ Wl = layer ? g_Whh1lo : g_Whh0lo;
    const float* __restrict__ bs = layer ? g_bsum1 : g_bsum0;

    // ---- one-time weight preload: 2 splits x 16 stages x 32 rows x 64 k ----
    for (int it = 0; it < 32; it++){
        int cid = it * 256 + tid;                // 8192 chunks of 16B
        int sp = cid >> 12;
        int rem = cid & 4095;
        int stg = rem >> 8;
        int r2 = rem & 255;
        int row = r2 >> 3, kc = (r2 & 7) << 3;
        const __nv_bfloat16* src = (sp ? Wl : Wh) + (size_t)(c0 + row) * HID + stg*64 + kc;
        unsigned dst = smb + (unsigned)(sp * 73728 + stg * 4608 + (row*72 + kc) * 2);
        cpasync16(dst, src);
    }
    cpcommit(); cpwait0(); __syncthreads();

    // epilogue index mapping (2 points per thread) + loop-invariant hoists
    const int jl0 = tid & 7, b_0 = tid >> 3;
    const int jglob = blockIdx.x * 8 + jl0;
    const float bsi = bs[jglob];
    const float bsf = bs[HID + jglob];
    const float bsg = bs[2*HID + jglob];
    const float bso = bs[3*HID + jglob];
    const int lt0 = (layer && lengths) ? (lengths[b_0]      - 1) : -9;
    const int lt1 = (layer && lengths) ? (lengths[b_0 + 32] - 1) : -9;
    const unsigned bargrp = (unsigned)(blockIdx.x & (NGRP - 1)) * 64u;

    unsigned gen = 0;
    for (int t = 0; t < TT; t++){
        const float* __restrict__ xpt = g_xproj + (size_t)t * (BB * NG);
        // ---- prefetch epilogue operands (independent of GEMM) ----
        float pxi[2], pxf[2], pxg[2], pxo[2], pcp[2];
#pragma unroll
        for (int pp = 0; pp < 2; pp++){
            int b = b_0 + pp * 32;
            pxi[pp] = xpt[b*NG + jglob];
            pxf[pp] = xpt[b*NG + HID + jglob];
            pxg[pp] = xpt[b*NG + 2*HID + jglob];
            pxo[pp] = xpt[b*NG + 3*HID + jglob];
            pcp[pp] = t ? g_cbuf[((t-1) & 1) * (BB*HID) + b*HID + jglob] : 0.f;
        }

        float cfr[2][4] = {{0.f,0.f,0.f,0.f},{0.f,0.f,0.f,0.f}};
        if (t > 0){
            const __nv_bfloat16* ah = layer ? (g_h1hi + (size_t)((t-1) & 1) * (BB*HID))
                                            : (g_h0hi + (size_t)(t-1) * (BB*HID));
            const __nv_bfloat16* al = layer ? (g_h1lo + (size_t)((t-1) & 1) * (BB*HID))
                                            : (g_h0lo + (size_t)(t-1) * (BB*HID));
            auto load_h = [&](int s){
                unsigned buf = smb + HR_OFF + (unsigned)((s & 3) * 18432);
                int kt = s << 6;
#pragma unroll
                for (int i = 0; i < 4; i++){
                    int cid = tid + (i << 8);         // 1024 chunks: hi 512 + lo 512
                    int sp = cid >> 9, rem = cid & 511;
                    int row = rem >> 3, kc = (rem & 7) << 3;
                    const __nv_bfloat16* src = (sp ? al : ah) + row*HID + kt + kc;
                    unsigned dst = buf + (unsigned)(sp * 9216 + (row*72 + kc) * 2);
                    cpasync16(dst, src);
                }
            };
            load_h(0); cpcommit();
            load_h(1); cpcommit();
            load_h(2); cpcommit();
#pragma unroll 1
            for (int s = 0; s < 16; s++){
                cpwait2();
                __syncthreads();
                if (s + 3 < 16) load_h(s + 3);
                cpcommit();
                unsigned wbh = smb + (unsigned)(s * 4608);
                unsigned wbl = wbh + WLO_OFF;
                unsigned hbh = smb + HR_OFF + (unsigned)((s & 3) * 18432);
                unsigned hbl = hbh + 9216u;
#pragma unroll
                for (int kk = 0; kk < 64; kk += 16){
                    unsigned ah4[4], al4[4], bh4[4], bl4[4];
                    ldsm4(hbh + (unsigned)((a_r*72 + kk + a_c) * 2), ah4[0], ah4[1], ah4[2], ah4[3]);
                    ldsm4(hbl + (unsigned)((a_r*72 + kk + a_c) * 2), al4[0], al4[1], al4[2], al4[3]);
                    ldsm4(wbh + (unsigned)((b_r*72 + kk + b_c) * 2), bh4[0], bh4[1], bh4[2], bh4[3]);
                    ldsm4(wbl + (unsigned)((b_r*72 + kk + b_c) * 2), bl4[0], bl4[1], bl4[2], bl4[3]);
                    mma_bf16(cfr[0], ah4, bh4[0], bh4[1]);
                    mma_bf16(cfr[0], ah4, bl4[0], bl4[1]);
                    mma_bf16(cfr[0], al4, bh4[0], bh4[1]);
                    mma_bf16(cfr[1], ah4, bh4[2], bh4[3]);
                    mma_bf16(cfr[1], ah4, bl4[2], bl4[3]);
                    mma_bf16(cfr[1], al4, bh4[2], bh4[3]);
                }
            }
        }
        // stage gate pre-activations to smem
        {
            int r0 = lane >> 2, tc = (lane & 3) << 1;
#pragma unroll
            for (int nf = 0; nf < 2; nf++){
                int col = wn*16 + nf*8 + tc;
                *(float2*)&gt[(wm*16 + r0) * 36 + col]     = make_float2(cfr[nf][0], cfr[nf][1]);
                *(float2*)&gt[(wm*16 + 8 + r0) * 36 + col] = make_float2(cfr[nf][2], cfr[nf][3]);
            }
        }
        __syncthreads();
#pragma unroll
        for (int pp = 0; pp < 2; pp++){
            int b = b_0 + pp * 32;
            float4 gv = *(float4*)&gt[b*36 + jl0*4];
            float vi = gv.x + bsi + pxi[pp];
            float vf = gv.y + bsf + pxf[pp];
            float vg = gv.z + bsg + pxg[pp];
            float vo = gv.w + bso + pxo[pp];
            float is = 1.f / (1.f + __expf(-vi));
            float fs = 1.f / (1.f + __expf(-vf));
            float gs = tanhf(vg);
            float os = 1.f / (1.f + __expf(-vo));
            float cn = fs * pcp[pp] + is * gs;
            float hn = os * tanhf(cn);
            g_cbuf[(t & 1) * (BB*HID) + b*HID + jglob] = cn;
            __nv_bfloat16 hh = __float2bfloat16(hn);
            __nv_bfloat16 hl = __float2bfloat16(hn - __bfloat162float(hh));
            if (layer){
                g_h1hi[(t & 1) * (BB*HID) + b*HID + jglob] = hh;
                g_h1lo[(t & 1) * (BB*HID) + b*HID + jglob] = hl;
                int lt = pp ? lt1 : lt0;
                if (lt == t) fout[b*HID + jglob] = hn;
            } else {
                g_h0hi[(size_t)t * (BB*HID) + b*HID + jglob] = hh;
                g_h0lo[(size_t)t * (BB*HID) + b*HID + jglob] = hl;
            }
        }
        // -------- two-level grid barrier (spread counters + root, sense-reversal) --------
        __syncthreads();
        if (tid == 0){
            __threadfence();
            if (atomicAdd(&g_cnt[bargrp], 1u) == GRPSZ - 1){
                if (atomicAdd(&g_root, 1u) == NGRP - 1){
                    g_root = 0;
#pragma unroll
                    for (int i = 0; i < NGRP; i++) g_cnt[i*64] = 0;
                    __threadfence();
                    g_sense = gen + 1;
                } else {
                    while (g_sense == gen) __nanosleep(32);
                }
            } else {
                while (g_sense == gen) __nanosleep(32);
            }
            __threadfence();
        }
        __syncthreads();
        gen++;
    }
}

// ---------------- host ----------------
extern "C" void kernel_launch(void* const* d_in, const int* in_sizes, int n_in,
                              void* d_out, int out_size) {
    const int*   x    = (const int*)  d_in[0];
    const int*   lens = (const int*)  d_in[1];
    const float* emb  = (const float*)d_in[2];
    const float* Wih0 = (const float*)d_in[3];
    const float* bih0 = (const float*)d_in[4];
    const float* Aih0 = (const float*)d_in[5];
    const float* Bih0 = (const float*)d_in[6];
    const float* Whh0 = (const float*)d_in[7];
    const float* bhh0 = (const float*)d_in[8];
    const float* Ahh0 = (const float*)d_in[9];
    const float* Bhh0 = (const float*)d_in[10];
    const float* Wih1 = (const float*)d_in[11];
    const float* bih1 = (const float*)d_in[12];
    const float* Aih1 = (const float*)d_in[13];
    const float* Bih1 = (const float*)d_in[14];
    const float* Whh1 = (const float*)d_in[15];
    const float* bhh1 = (const float*)d_in[16];
    const float* Ahh1 = (const float*)d_in[17];
    const float* Bhh1 = (const float*)d_in[18];
    float* out = (float*)d_out;

    cudaFuncSetAttribute(gemm_hmma,  cudaFuncAttributeMaxDynamicSharedMemorySize, 61440);
    cudaFuncSetAttribute(recur_hmma, cudaFuncAttributeMaxDynamicSharedMemorySize, 230400);

    // launch order chosen so recur_hmma(layer 0) is launch index 5 (ncu -s 5 -c 1 captures it)
    prep_bias_kernel<<<32, 256>>>(bih0, bhh0, bih1, bhh1);                    // 0
    prep_w_all<<<(EMB*NG + 3*HID*NG) / 256, 256>>>(Wih0, Aih0, Bih0,          // 1
                                                   Wih1, Aih1, Bih1,
                                                   Whh0, Ahh0, Bhh0,
                                                   Whh1, Ahh1, Bhh1);
    gather_x0<<<(MROWS * EMB) / 256, 256>>>(x, emb);                          // 2
    bar_reset<<<1, 32>>>();                                                   // 3
    gemm_hmma<<<dim3(32, 512), 256, 61440>>>(0, EMB);                         // 4
    recur_hmma<<<NCTA, 256, 230400>>>(0, (const int*)0, (float*)0);           // 5  <- profiled
    bar_reset<<<1, 32>>>();                                                   // 6
    gemm_hmma<<<dim3(32, 512), 256, 61440>>>(1, HID);                         // 7
    recur_hmma<<<NCTA, 256, 230400>>>(1, lens, out);                          // 8
}